// round 6
// baseline (speedup 1.0000x reference)
#include <cuda_runtime.h>

#define NTHREADS 512
#define TLEN 4096

// exchange-buffer swizzle: conflict-free for (row=k1 per-lane, col=g) writes AND
// (row=g, col per-lane) reads -- derived bitwise for half-warp phases
#define XI(k1,n2) (((k1)<<6) | (((n2) ^ ((k1)&6) ^ (((k1)&1)<<3)) & 63))
// natural-order buffer swizzle: conflict-free for t = g + 64*(l3+8d) writes
#define I01(t) ((t) ^ ((((t)>>6)&7)<<1))

__device__ float4 g_masks[TLEN];   // (S0,S1,S2,0) with 0.5/4096 folded in
__device__ float2 g_tw[1024];      // exp(-2*pi*i*j/4096)

struct __align__(16) Smem {
    float2 A[TLEN];        // four-step exchange scratch
    float2 B[TLEN];        // Y2 park (private pattern), then mode2 at I01
    float2 C[TLEN];        // modes01 at I01
    float2 tw[1024];
    int    hist[16][36];
    float  red[16][20];
    float  totals[20];
    int    cnt[36];
    float  xnyq;
};

__device__ __forceinline__ float2 cadd(float2 a, float2 b){ return make_float2(a.x+b.x, a.y+b.y); }
__device__ __forceinline__ float2 csub(float2 a, float2 b){ return make_float2(a.x-b.x, a.y-b.y); }
__device__ __forceinline__ float2 cmul(float2 a, float2 b){
    return make_float2(fmaf(a.x,b.x,-a.y*b.y), fmaf(a.x,b.y, a.y*b.x));
}

__global__ void init_tables()
{
    int j = blockIdx.x * blockDim.x + threadIdx.x;   // 0..4095
    if (j < 1024) {
        float sv, cv;
        sincospif(-(float)j * (1.0f/2048.0f), &sv, &cv); // -2*pi*j/4096
        g_tw[j] = make_float2(cv, sv);
    }
    float f = (float)((j < 2048) ? j : (j - 4096)) * (1.0f/4096.0f);
    const float h = 0.5f * (1.0f/4096.0f);
    float u;
    u = f + 0.5f; float a0 = expf(-12.5f*u*u);
    u = f - 0.5f; float a1 = expf(-12.5f*u*u);
    u = f - 0.3f; float b0 = expf(-12.5f*u*u);
    u = f + 0.3f; float b1 = expf(-12.5f*u*u);
    u = f - 0.1f; float c0 = expf(-12.5f*u*u);
    u = f + 0.1f; float c1 = expf(-12.5f*u*u);
    g_masks[j] = make_float4(h*(a0+a1), h*(b0+b1), h*(c0+c1), 0.f);
}

// W4096^t (forward sign), t in [0,4096)
__device__ __forceinline__ float2 twid_f(const float2* __restrict__ tw, int t)
{
    int q = (t >> 10) & 3, r = t & 1023;
    float2 w = tw[r];
    if (q == 1) return make_float2( w.y, -w.x);   // * -i
    if (q == 2) return make_float2(-w.x, -w.y);   // * -1
    if (q == 3) return make_float2(-w.y,  w.x);   // * +i
    return w;
}
template<bool INV>
__device__ __forceinline__ float2 twid(const float2* __restrict__ tw, int t)
{
    float2 w = twid_f(tw, t);
    if (INV) w.y = -w.y;
    return w;
}

// In-place DFT-8: x[r] <- sum_n x[n] * W8^(+-rn)
template<bool INV>
__device__ __forceinline__ void dft8(float2 x[8])
{
    float2 t0=cadd(x[0],x[4]), t1=cadd(x[1],x[5]), t2=cadd(x[2],x[6]), t3=cadd(x[3],x[7]);
    float2 u0=csub(x[0],x[4]), u1=csub(x[1],x[5]), u2=csub(x[2],x[6]), u3=csub(x[3],x[7]);
    const float C8 = 0.70710678118654752f;
    const float2 om  = INV ? make_float2( C8,  C8) : make_float2( C8, -C8);
    const float2 om3 = INV ? make_float2(-C8,  C8) : make_float2(-C8, -C8);
    float2 v1 = cmul(u1, om);
    float2 v2 = INV ? make_float2(-u2.y, u2.x) : make_float2(u2.y, -u2.x);
    float2 v3 = cmul(u3, om3);
    float2 s02=cadd(t0,t2), d02=csub(t0,t2), s13=cadd(t1,t3), d13=csub(t1,t3);
    float2 jd = make_float2(-d13.y, d13.x);
    x[0] = cadd(s02, s13);
    x[4] = csub(s02, s13);
    x[2] = INV ? cadd(d02, jd) : csub(d02, jd);
    x[6] = INV ? csub(d02, jd) : cadd(d02, jd);
    float2 so=cadd(u0,v2), doo=csub(u0,v2), s13o=cadd(v1,v3), d13o=csub(v1,v3);
    float2 jdo = make_float2(-d13o.y, d13o.x);
    x[1] = cadd(so, s13o);
    x[5] = csub(so, s13o);
    x[3] = INV ? cadd(doo, jdo) : csub(doo, jdo);
    x[7] = INV ? csub(doo, jdo) : cadd(doo, jdo);
}

// 8x8 register transpose across an 8-lane shuffle group (hypercube exchange).
__device__ __forceinline__ void transpose8(float2 v[8], int l3)
{
    #pragma unroll
    for (int bm = 1; bm < 8; bm <<= 1) {
        #pragma unroll
        for (int i = 0; i < 8; ++i) {
            if (!(i & bm)) {
                int ip = i | bm;
                bool up = (l3 & bm) != 0;
                float2 give = up ? v[i] : v[ip];
                float2 got;
                got.x = __shfl_xor_sync(0xffffffffu, give.x, bm, 8);
                got.y = __shfl_xor_sync(0xffffffffu, give.y, bm, 8);
                if (up) v[i] = got; else v[ip] = got;
            }
        }
    }
}

// FFT-64 within an 8-lane group. In: v[m] = data[8m + l3]. Out: v[d] = OUT[l3 + 8d].
template<bool INV>
__device__ __forceinline__ void fft64_group(float2 v[8], int l3,
                                            const float2* __restrict__ tw)
{
    dft8<INV>(v);                                 // P[c] in slot c
    #pragma unroll
    for (int c = 1; c < 8; ++c)                   // * W64^(l3*c)
        v[c] = cmul(v[c], twid<INV>(tw, 64*l3*c));
    transpose8(v, l3);                            // lane c <- P'_b[c] in slot b
    dft8<INV>(v);                                 // OUT[c + 8d] in slot d
}

// 4096-pt FFT, four-step, register resident.
// In:  v[m] = data[64*(8m+l3) + g]     Out: v[d] = OUT[g + 64*(l3+8d)]
template<bool INV>
__device__ __forceinline__ void fft4step(float2 v[8], int g, int l3,
                                         const float2* __restrict__ tw,
                                         float2* __restrict__ xch)
{
    fft64_group<INV>(v, l3, tw);                  // v[d] = A[k1 = l3+8d], column g
    #pragma unroll
    for (int d2 = 0; d2 < 8; ++d2) {              // four-step twiddle W^(g*k1)
        int k1 = l3 + 8*d2;
        v[d2] = cmul(v[d2], twid<INV>(tw, g*k1));
        xch[XI(k1, g)] = v[d2];
    }
    __syncthreads();
    #pragma unroll
    for (int m = 0; m < 8; ++m)                   // row g, cols l3+8m
        v[m] = xch[XI(g, l3 + 8*m)];
    fft64_group<INV>(v, l3, tw);                  // v[d] = OUT[g + 64*(l3+8d)]
    __syncthreads();                              // xch reusable
}

// Lehmer code of stable argsort of (a,b,c), matching reference id formula.
__device__ __forceinline__ int permid(float a, float b, float c)
{
    int i0 = (a <= b) ? 1 : 0;
    int i1 = (a <= c) ? 1 : 0;
    int i2 = (b <= c) ? 1 : 0;
    int idx = (i0 << 2) | (i1 << 1) | i2;
    const unsigned LUT = (5u<<0)|(3u<<4)|(0u<<8)|(2u<<12)|(4u<<16)|(0u<<20)|(1u<<24)|(0u<<28);
    return (int)((LUT >> (idx*4)) & 0xFu);
}

__device__ __forceinline__ constexpr int qidx(int k, int l) { return k*(9-k)/2 + l; }

__global__ __launch_bounds__(NTHREADS, 2)
void tfmptf_kernel(const float* __restrict__ in, float* __restrict__ out)
{
    extern __shared__ char smraw[];
    Smem& sm = *reinterpret_cast<Smem*>(smraw);
    const int tid = threadIdx.x;
    const int bid = blockIdx.x;          // bid = b*64 + d
    const int d = bid & 63;
    const int b = bid >> 6;
    const int warp = tid >> 5;
    const int lane = tid & 31;
    const int g  = tid >> 3;             // shuffle-group = column index
    const int l3 = tid & 7;              // lane within group

    // --- tables + hist zero ---
    for (int j = tid; j < 1024; j += NTHREADS)
        sm.tw[j] = g_tw[j];
    for (int i = tid; i < 16*36; i += NTHREADS) ((int*)sm.hist)[i] = 0;
    __syncthreads();

    // --- load input into registers: v[m] = x[t], t = 512m + 64*l3 + g ---
    const float* xin = in + ((long)b * TLEN) * 64 + d;
    float2 v[8];
    #pragma unroll
    for (int m = 0; m < 8; ++m)
        v[m] = make_float2(__ldg(&xin[(long)(512*m + 64*l3 + g) * 64]), 0.0f);

    // --- forward FFT: v[d2] = X[g + 64*(l3+8d2)] ---
    fft4step<false>(v, g, l3, sm.tw, sm.A);

    // --- masks in regs; park Y2; Y1 stays in v ---
    #pragma unroll
    for (int d2 = 0; d2 < 8; ++d2) {
        int K = g + 64*(l3 + 8*d2);
        float2 X = v[d2];
        if (K == 2048) sm.xnyq = X.x;
        float4 S = __ldg(&g_masks[K]);
        sm.B[d2*512 + tid] = make_float2(X.x*S.z, X.y*S.z);     // Y2 park (private)
        v[d2] = make_float2(X.x*S.x - X.y*S.y, X.x*S.y + X.y*S.x);
    }

    // --- IFFT #1: v[d2] = modes01 at t = g + 64*(l3+8d2) ---
    fft4step<true>(v, g, l3, sm.tw, sm.A);
    #pragma unroll
    for (int d2 = 0; d2 < 8; ++d2) {
        int t = g + 64*(l3 + 8*d2);
        sm.C[I01(t)] = v[d2];
    }

    // --- IFFT #2 from parked Y2 (same thread, same slots) ---
    #pragma unroll
    for (int m = 0; m < 8; ++m)
        v[m] = sm.B[m*512 + tid];
    fft4step<true>(v, g, l3, sm.tw, sm.A);
    #pragma unroll
    for (int d2 = 0; d2 < 8; ++d2) {
        int t = g + 64*(l3 + 8*d2);
        sm.B[I01(t)] = make_float2(v[d2].x, 0.f);               // mode2
    }

    // --- Nyquist rank-1 corrections ---
    const float xn = sm.xnyq * (1.0f/4096.0f);
    const float eg[3] = {
        0.49999813667341397f * xn,
        0.30309759854236545f * xn,
        0.06211314334918520f * xn
    };

    // --- correlation moments (own t-set: modes01 from own C writes, mode2 in regs) ---
    float S[5]; float Q[15];
    #pragma unroll
    for (int i = 0; i < 5; ++i) S[i] = 0.f;
    #pragma unroll
    for (int i = 0; i < 15; ++i) Q[i] = 0.f;
    const float pe = (g & 1) ? -1.f : 1.f;       // parity of t = g + 64*(...)
    #pragma unroll
    for (int d2 = 0; d2 < 8; ++d2) {
        int t = g + 64*(l3 + 8*d2);
        float2 z = sm.C[I01(t)];
        float m2 = v[d2].x;
        float vv[5];
        vv[0] = z.x + pe*eg[0];
        vv[1] = z.y + pe*eg[1];
        vv[2] = m2  + pe*eg[2];
        vv[3] = m2  - pe*eg[2];
        vv[4] = z.y - pe*eg[1];
        float e[5];
        #pragma unroll
        for (int kk = 0; kk < 5; ++kk) e[kk] = vv[kk]*vv[kk];
        #pragma unroll
        for (int kk = 0; kk < 5; ++kk) {
            S[kk] += e[kk];
            #pragma unroll
            for (int l = kk; l < 5; ++l)
                Q[qidx(kk,l)] = fmaf(e[kk], e[l], Q[qidx(kk,l)]);
        }
    }
    {
        float vvv[20];
        #pragma unroll
        for (int j = 0; j < 5; ++j)  vvv[j]   = S[j];
        #pragma unroll
        for (int j = 0; j < 15; ++j) vvv[5+j] = Q[j];
        #pragma unroll
        for (int j = 0; j < 20; ++j)
            #pragma unroll
            for (int off = 16; off; off >>= 1)
                vvv[j] += __shfl_down_sync(0xffffffffu, vvv[j], off);
        if (lane == 0)
            #pragma unroll
            for (int j = 0; j < 20; ++j) sm.red[warp][j] = vvv[j];
    }
    __syncthreads();   // C + B(mode2) + red visible to all

    // --- sliding-window permutation transitions: 5 modes, 4093 transitions ---
    {
        const int w0 = tid * 8;
        float2 z01[11]; float m2v[11];
        #pragma unroll
        for (int i = 0; i < 11; ++i) {
            int e = w0 + i; e = (e < TLEN) ? e : (TLEN - 1);
            z01[i] = sm.C[I01(e)];
            m2v[i] = sm.B[I01(e)].x;
        }
        #pragma unroll
        for (int gg = 0; gg < 3; ++gg) {
            float mv[11];
            #pragma unroll
            for (int i = 0; i < 11; ++i)
                mv[i] = (gg == 0) ? z01[i].x : ((gg == 1) ? z01[i].y : m2v[i]);
            const int nsign = (gg == 0) ? 1 : 2;
            #pragma unroll
            for (int sv = 0; sv < 2; ++sv) {
                if (sv >= nsign) break;
                const float eps = (sv == 0) ? eg[gg] : -eg[gg];
                float vv[11];
                #pragma unroll
                for (int i = 0; i < 11; ++i)
                    vv[i] = mv[i] + (((w0 + i) & 1) ? -eps : eps);
                int id[9];
                #pragma unroll
                for (int i = 0; i < 9; ++i)
                    id[i] = permid(vv[i], vv[i+1], vv[i+2]);
                #pragma unroll
                for (int i = 0; i < 8; ++i) {
                    bool valid = (w0 + i) < 4093;
                    int code = valid ? (id[i]*6 + id[i+1]) : 36;
                    unsigned grp = __match_any_sync(0xffffffffu, code);
                    if (valid && (int)(__ffs(grp) - 1) == lane)
                        atomicAdd(&sm.hist[warp][code], __popc(grp));
                }
            }
        }
    }
    __syncthreads();

    if (tid < 36) {
        int ctot = 0;
        #pragma unroll
        for (int w = 0; w < 16; ++w) ctot += sm.hist[w][tid];
        sm.cnt[tid] = ctot;
    }
    if (tid < 20) {
        float tot = 0.f;
        #pragma unroll
        for (int w = 0; w < 16; ++w) tot += sm.red[w][tid];
        sm.totals[tid] = tot;
    }
    __syncthreads();

    float* outbd = out + (long)bid * 46;
    if (tid < 36) {
        int p = tid / 6;
        int rs = 0;
        #pragma unroll
        for (int q = 0; q < 6; ++q) rs += sm.cnt[p*6 + q];
        float denom = rs ? (float)rs : 1.0f;
        outbd[tid] = (float)sm.cnt[tid] / denom;
    }
    if (tid == 0) {
        const float invT = 1.0f / 4096.0f;
        float cov[15];
        #pragma unroll
        for (int k = 0; k < 5; ++k)
            #pragma unroll
            for (int l = k; l < 5; ++l)
                cov[qidx(k,l)] = sm.totals[5 + qidx(k,l)]
                               - sm.totals[k]*sm.totals[l]*invT;
        float dstd[5];
        #pragma unroll
        for (int k = 0; k < 5; ++k) dstd[k] = sqrtf(fmaxf(cov[qidx(k,k)], 0.f));
        int oi = 36;
        #pragma unroll
        for (int k = 0; k < 5; ++k) {
            #pragma unroll
            for (int l = k+1; l < 5; ++l) {
                float den = dstd[k] * dstd[l];
                float r = (den > 0.f) ? cov[qidx(k,l)] / den : 0.f;
                r = fminf(1.f, fmaxf(-1.f, r));
                outbd[oi++] = r;
            }
        }
    }
}

extern "C" void kernel_launch(void* const* d_in, const int* in_sizes, int n_in,
                              void* d_out, int out_size)
{
    (void)in_sizes; (void)n_in; (void)out_size;
    const float* in = (const float*)d_in[0];
    float* out = (float*)d_out;
    init_tables<<<8, 512>>>();
    cudaFuncSetAttribute(tfmptf_kernel, cudaFuncAttributeMaxDynamicSharedMemorySize,
                         (int)sizeof(Smem));
    tfmptf_kernel<<<1024, NTHREADS, sizeof(Smem)>>>(in, out);
}

// round 8
// speedup vs baseline: 1.2379x; 1.2379x over previous
#include <cuda_runtime.h>

#define NTHREADS 512
#define TLEN 4096

// bank swizzle: conflict-free for strides 512/64/8/1 (verified per half-warp)
#define PH(e) ((e) ^ ((((unsigned)(e))>>3)&7u) ^ (((((unsigned)(e))>>6)&1u)<<3))

__device__ float4 g_masks_br[TLEN];  // masks at digit-reversed position, 1/4096 folded
__device__ float2 g_tw512[512];      // W4096^j
__device__ float2 g_t8[64];          // W4096^(8j)  = W512^j
__device__ float2 g_t64[8];          // W4096^(64j) = W64^j

struct __align__(16) Smem {
    float2 buf0[TLEN];     // Y1 path -> modes01 (natural, PH layout)
    float2 buf1[TLEN];     // Y2 path -> mode2 in .x
    float2 tw512[512];
    float2 t8[64];
    float2 t64[8];
    int    hist[8][36];
    float  red[16][20];
    float  totals[20];
    int    cnt[36];
    float  xnyq;
};

__device__ __forceinline__ float2 cadd(float2 a, float2 b){ return make_float2(a.x+b.x, a.y+b.y); }
__device__ __forceinline__ float2 csub(float2 a, float2 b){ return make_float2(a.x-b.x, a.y-b.y); }
__device__ __forceinline__ float2 cmul(float2 a, float2 b){
    return make_float2(fmaf(a.x,b.x,-a.y*b.y), fmaf(a.x,b.y, a.y*b.x));
}
__device__ __forceinline__ float2 conj2(float2 a){ return make_float2(a.x, -a.y); }

__global__ void init_tables()
{
    int j = blockIdx.x * blockDim.x + threadIdx.x;   // 0..4095
    float sv, cv;
    if (j < 512) {
        sincospif(-(float)j * (1.0f/2048.0f), &sv, &cv);  // -2pi j/4096
        g_tw512[j] = make_float2(cv, sv);
    }
    if (j < 64) {
        sincospif(-(float)j * (1.0f/256.0f), &sv, &cv);   // -2pi 8j/4096
        g_t8[j] = make_float2(cv, sv);
    }
    if (j < 8) {
        sincospif(-(float)j * (1.0f/32.0f), &sv, &cv);    // -2pi 64j/4096
        g_t64[j] = make_float2(cv, sv);
    }
    // frequency bin at digit-reversed position j (4 base-8 digits)
    int K = ((j&7)<<9) | (((j>>3)&7)<<6) | (((j>>6)&7)<<3) | ((j>>9)&7);
    float f = (float)((K < 2048) ? K : (K - 4096)) * (1.0f/4096.0f);
    const float h = 0.5f * (1.0f/4096.0f);
    float u;
    u = f + 0.5f; float a0 = expf(-12.5f*u*u);
    u = f - 0.5f; float a1 = expf(-12.5f*u*u);
    u = f - 0.3f; float b0 = expf(-12.5f*u*u);
    u = f + 0.3f; float b1 = expf(-12.5f*u*u);
    u = f - 0.1f; float c0 = expf(-12.5f*u*u);
    u = f + 0.1f; float c1 = expf(-12.5f*u*u);
    g_masks_br[j] = make_float4(h*(a0+a1), h*(b0+b1), h*(c0+c1), 0.f);
}

// In-place DFT-8: x[r] <- sum_n x[n] * W8^(+-rn)
template<bool INV>
__device__ __forceinline__ void dft8(float2 x[8])
{
    float2 t0=cadd(x[0],x[4]), t1=cadd(x[1],x[5]), t2=cadd(x[2],x[6]), t3=cadd(x[3],x[7]);
    float2 u0=csub(x[0],x[4]), u1=csub(x[1],x[5]), u2=csub(x[2],x[6]), u3=csub(x[3],x[7]);
    const float C8 = 0.70710678118654752f;
    const float2 om  = INV ? make_float2( C8,  C8) : make_float2( C8, -C8);
    const float2 om3 = INV ? make_float2(-C8,  C8) : make_float2(-C8, -C8);
    float2 v1 = cmul(u1, om);
    float2 v2 = INV ? make_float2(-u2.y, u2.x) : make_float2(u2.y, -u2.x);
    float2 v3 = cmul(u3, om3);
    float2 s02=cadd(t0,t2), d02=csub(t0,t2), s13=cadd(t1,t3), d13=csub(t1,t3);
    float2 jd = make_float2(-d13.y, d13.x);
    x[0] = cadd(s02, s13);
    x[4] = csub(s02, s13);
    x[2] = INV ? cadd(d02, jd) : csub(d02, jd);
    x[6] = INV ? csub(d02, jd) : cadd(d02, jd);
    float2 so=cadd(u0,v2), doo=csub(u0,v2), s13o=cadd(v1,v3), d13o=csub(v1,v3);
    float2 jdo = make_float2(-d13o.y, d13o.x);
    x[1] = cadd(so, s13o);
    x[5] = csub(so, s13o);
    x[3] = INV ? cadd(doo, jdo) : csub(doo, jdo);
    x[7] = INV ? csub(doo, jdo) : cadd(doo, jdo);
}

// In-place forward DIF stage, M = 8^?; wb = W_L^j (L = 8M), twiddle AFTER dft.
template<int MB>
__device__ __forceinline__ void stage_fwd(float2* __restrict__ buf, int tid, float2 wb)
{
    const int M = 1 << MB;
    const int j = tid & (M-1);
    const int base = ((tid >> MB) << (MB+3)) | j;
    float2 x[8];
    #pragma unroll
    for (int k = 0; k < 8; ++k) x[k] = buf[PH(base + (k<<MB))];
    dft8<false>(x);
    float2 w = wb;
    #pragma unroll
    for (int r = 1; r < 8; ++r) { x[r] = cmul(x[r], w); if (r < 7) w = cmul(w, wb); }
    #pragma unroll
    for (int k = 0; k < 8; ++k) buf[PH(base + (k<<MB))] = x[k];
}

// In-place dual inverse DIT stage (both buffers, shared twiddles, BEFORE dft).
// wb must already be conjugated.
template<int MB>
__device__ __forceinline__ void stage_inv2(float2* __restrict__ b0,
                                           float2* __restrict__ b1,
                                           int tid, float2 wb)
{
    const int M = 1 << MB;
    const int j = tid & (M-1);
    const int base = ((tid >> MB) << (MB+3)) | j;
    float2 p[8], q[8];
    #pragma unroll
    for (int k = 0; k < 8; ++k) {
        int a = PH(base + (k<<MB));
        p[k] = b0[a]; q[k] = b1[a];
    }
    float2 w = wb;
    #pragma unroll
    for (int r = 1; r < 8; ++r) {
        p[r] = cmul(p[r], w); q[r] = cmul(q[r], w);
        if (r < 7) w = cmul(w, wb);
    }
    dft8<true>(p); dft8<true>(q);
    #pragma unroll
    for (int k = 0; k < 8; ++k) {
        int a = PH(base + (k<<MB));
        b0[a] = p[k]; b1[a] = q[k];
    }
}

// Lehmer code of stable argsort of (a,b,c), matching reference id formula.
__device__ __forceinline__ int permid(float a, float b, float c)
{
    int i0 = (a <= b) ? 1 : 0;
    int i1 = (a <= c) ? 1 : 0;
    int i2 = (b <= c) ? 1 : 0;
    int idx = (i0 << 2) | (i1 << 1) | i2;
    const unsigned LUT = (5u<<0)|(3u<<4)|(0u<<8)|(2u<<12)|(4u<<16)|(0u<<20)|(1u<<24)|(0u<<28);
    return (int)((LUT >> (idx*4)) & 0xFu);
}

__device__ __forceinline__ constexpr int qidx(int k, int l) { return k*(9-k)/2 + l; }

__global__ __launch_bounds__(NTHREADS, 3)
void tfmptf_kernel(const float* __restrict__ in, float* __restrict__ out)
{
    extern __shared__ char smraw[];
    Smem& sm = *reinterpret_cast<Smem*>(smraw);
    const int tid = threadIdx.x;
    const int bid = blockIdx.x;          // bid = b*64 + d
    const int d = bid & 63;
    const int b = bid >> 6;
    const int warp = tid >> 5;
    const int lane = tid & 31;

    // --- tables + hist zero (no barrier needed before stage 0: own-index use) ---
    float2 myw = __ldg(&g_tw512[tid]);
    sm.tw512[tid] = myw;
    if (tid < 64) sm.t8[tid]  = __ldg(&g_t8[tid]);
    if (tid < 8)  sm.t64[tid] = __ldg(&g_t64[tid]);
    for (int i = tid; i < 8*36; i += NTHREADS) ((int*)sm.hist)[i] = 0;

    // --- forward stage 0 (M=512): gmem -> butterfly -> buf0 ---
    const float* xin = in + ((long)b * TLEN) * 64 + d;
    {
        float2 x[8];
        #pragma unroll
        for (int k = 0; k < 8; ++k)
            x[k] = make_float2(__ldg(&xin[(long)(tid + (k<<9)) * 64]), 0.0f);
        dft8<false>(x);
        float2 w = myw;
        #pragma unroll
        for (int r = 1; r < 8; ++r) { x[r] = cmul(x[r], w); if (r < 7) w = cmul(w, myw); }
        #pragma unroll
        for (int k = 0; k < 8; ++k) sm.buf0[PH(tid + (k<<9))] = x[k];
    }
    __syncthreads();

    // --- forward stages 1 (M=64), 2 (M=8) ---
    stage_fwd<6>(sm.buf0, tid, sm.t8[tid & 63]);
    __syncthreads();
    stage_fwd<3>(sm.buf0, tid, sm.t64[tid & 7]);
    __syncthreads();

    // --- fused: fwd stage 3 (trivial tw) + masks (bitrev table) + inv stage 0 ---
    {
        const int base = tid << 3;
        float2 y[8];
        #pragma unroll
        for (int k = 0; k < 8; ++k) y[k] = sm.buf0[PH(base + k)];
        dft8<false>(y);
        if (tid == 0) sm.xnyq = y[4].x;          // pos 4 = rev(2048)
        float2 z2[8];
        #pragma unroll
        for (int k = 0; k < 8; ++k) {
            float4 S = __ldg(&g_masks_br[base + k]);
            float2 Y = y[k];
            z2[k] = make_float2(Y.x*S.z, Y.y*S.z);
            y[k]  = make_float2(Y.x*S.x - Y.y*S.y, Y.x*S.y + Y.y*S.x);
        }
        dft8<true>(y); dft8<true>(z2);
        #pragma unroll
        for (int k = 0; k < 8; ++k) {
            int a = PH(base + k);
            sm.buf0[a] = y[k]; sm.buf1[a] = z2[k];
        }
    }
    __syncthreads();

    // --- dual inverse stages: L=64 (M=8), L=512 (M=64) ---
    stage_inv2<3>(sm.buf0, sm.buf1, tid, conj2(sm.t64[tid & 7]));
    __syncthreads();
    stage_inv2<6>(sm.buf0, sm.buf1, tid, conj2(sm.t8[tid & 63]));
    __syncthreads();

    // --- final dual inverse stage (L=4096, M=512), keep results in regs ---
    float2 p[8], q[8];
    {
        #pragma unroll
        for (int k = 0; k < 8; ++k) {
            int a = PH(tid + (k<<9));
            p[k] = sm.buf0[a]; q[k] = sm.buf1[a];
        }
        float2 wb = conj2(myw);
        float2 w = wb;
        #pragma unroll
        for (int r = 1; r < 8; ++r) {
            p[r] = cmul(p[r], w); q[r] = cmul(q[r], w);
            if (r < 7) w = cmul(w, wb);
        }
        dft8<true>(p); dft8<true>(q);
        #pragma unroll
        for (int k = 0; k < 8; ++k) {
            int a = PH(tid + (k<<9));
            sm.buf0[a] = p[k]; sm.buf1[a] = q[k];
        }
    }

    // --- Nyquist rank-1 corrections (xnyq visible since fused-stage barriers) ---
    const float xn = sm.xnyq * (1.0f/4096.0f);
    const float eg[3] = {
        0.49999813667341397f * xn,
        0.30309759854236545f * xn,
        0.06211314334918520f * xn
    };

    // --- correlation moments from registers (t = tid + 512k, parity = tid&1) ---
    float S[5]; float Q[15];
    #pragma unroll
    for (int i = 0; i < 5; ++i) S[i] = 0.f;
    #pragma unroll
    for (int i = 0; i < 15; ++i) Q[i] = 0.f;
    const float pe = (tid & 1) ? -1.f : 1.f;
    #pragma unroll
    for (int k = 0; k < 8; ++k) {
        float m0 = p[k].x, m1 = p[k].y, m2 = q[k].x;
        float vv[5];
        vv[0] = m0 + pe*eg[0];
        vv[1] = m1 + pe*eg[1];
        vv[2] = m2 + pe*eg[2];
        vv[3] = m2 - pe*eg[2];
        vv[4] = m1 - pe*eg[1];
        float e[5];
        #pragma unroll
        for (int kk = 0; kk < 5; ++kk) e[kk] = vv[kk]*vv[kk];
        #pragma unroll
        for (int kk = 0; kk < 5; ++kk) {
            S[kk] += e[kk];
            #pragma unroll
            for (int l = kk; l < 5; ++l)
                Q[qidx(kk,l)] = fmaf(e[kk], e[l], Q[qidx(kk,l)]);
        }
    }
    {
        float vvv[20];
        #pragma unroll
        for (int j = 0; j < 5; ++j)  vvv[j]   = S[j];
        #pragma unroll
        for (int j = 0; j < 15; ++j) vvv[5+j] = Q[j];
        #pragma unroll
        for (int j = 0; j < 20; ++j)
            #pragma unroll
            for (int off = 16; off; off >>= 1)
                vvv[j] += __shfl_down_sync(0xffffffffu, vvv[j], off);
        if (lane == 0)
            #pragma unroll
            for (int j = 0; j < 20; ++j) sm.red[warp][j] = vvv[j];
    }
    __syncthreads();   // modes stores + red visible

    // --- sliding-window permutation transitions: 5 modes, 4093 transitions ---
    {
        const int w0 = tid * 8;
        float2 z01[11]; float m2v[11];
        #pragma unroll
        for (int i = 0; i < 11; ++i) {
            int e = w0 + i; e = (e < TLEN) ? e : (TLEN - 1);
            int a = PH(e);
            z01[i] = sm.buf0[a];
            m2v[i] = sm.buf1[a].x;
        }
        #pragma unroll
        for (int gg = 0; gg < 3; ++gg) {
            float mv[11];
            #pragma unroll
            for (int i = 0; i < 11; ++i)
                mv[i] = (gg == 0) ? z01[i].x : ((gg == 1) ? z01[i].y : m2v[i]);
            const int nsign = (gg == 0) ? 1 : 2;
            #pragma unroll
            for (int sv = 0; sv < 2; ++sv) {
                if (sv >= nsign) break;
                const float eps = (sv == 0) ? eg[gg] : -eg[gg];
                float vv[11];
                #pragma unroll
                for (int i = 0; i < 11; ++i)
                    vv[i] = mv[i] + (((w0 + i) & 1) ? -eps : eps);
                int id[9];
                #pragma unroll
                for (int i = 0; i < 9; ++i)
                    id[i] = permid(vv[i], vv[i+1], vv[i+2]);
                #pragma unroll
                for (int i = 0; i < 8; ++i) {
                    bool valid = (w0 + i) < 4093;
                    int code = valid ? (id[i]*6 + id[i+1]) : 36;
                    unsigned grp = __match_any_sync(0xffffffffu, code);
                    if (valid && (int)(__ffs(grp) - 1) == lane)
                        atomicAdd(&sm.hist[warp >> 1][code], __popc(grp));
                }
            }
        }
    }
    __syncthreads();

    if (tid < 36) {
        int ctot = 0;
        #pragma unroll
        for (int w = 0; w < 8; ++w) ctot += sm.hist[w][tid];
        sm.cnt[tid] = ctot;
    }
    if (tid < 20) {
        float tot = 0.f;
        #pragma unroll
        for (int w = 0; w < 16; ++w) tot += sm.red[w][tid];
        sm.totals[tid] = tot;
    }
    __syncthreads();

    float* outbd = out + (long)bid * 46;
    if (tid < 36) {
        int pp = tid / 6;
        int rs = 0;
        #pragma unroll
        for (int qq = 0; qq < 6; ++qq) rs += sm.cnt[pp*6 + qq];
        float denom = rs ? (float)rs : 1.0f;
        outbd[tid] = (float)sm.cnt[tid] / denom;
    }
    if (tid == 0) {
        const float invT = 1.0f / 4096.0f;
        float cov[15];
        #pragma unroll
        for (int k = 0; k < 5; ++k)
            #pragma unroll
            for (int l = k; l < 5; ++l)
                cov[qidx(k,l)] = sm.totals[5 + qidx(k,l)]
                               - sm.totals[k]*sm.totals[l]*invT;
        float dstd[5];
        #pragma unroll
        for (int k = 0; k < 5; ++k) dstd[k] = sqrtf(fmaxf(cov[qidx(k,k)], 0.f));
        int oi = 36;
        #pragma unroll
        for (int k = 0; k < 5; ++k) {
            #pragma unroll
            for (int l = k+1; l < 5; ++l) {
                float den = dstd[k] * dstd[l];
                float r = (den > 0.f) ? cov[qidx(k,l)] / den : 0.f;
                r = fminf(1.f, fmaxf(-1.f, r));
                outbd[oi++] = r;
            }
        }
    }
}

extern "C" void kernel_launch(void* const* d_in, const int* in_sizes, int n_in,
                              void* d_out, int out_size)
{
    (void)in_sizes; (void)n_in; (void)out_size;
    const float* in = (const float*)d_in[0];
    float* out = (float*)d_out;
    init_tables<<<8, 512>>>();
    cudaFuncSetAttribute(tfmptf_kernel, cudaFuncAttributeMaxDynamicSharedMemorySize,
                         (int)sizeof(Smem));
    tfmptf_kernel<<<1024, NTHREADS, sizeof(Smem)>>>(in, out);
}

// round 9
// speedup vs baseline: 1.3037x; 1.0532x over previous
#include <cuda_runtime.h>

#define NTHREADS 512
#define TLEN 4096

// bank swizzle: conflict-free for strides 512/64/8/1 (verified per half-warp)
#define PH(e) ((e) ^ ((((unsigned)(e))>>3)&7u) ^ (((((unsigned)(e))>>6)&1u)<<3))

__device__ float4 g_masks_br[TLEN];  // masks at digit-reversed position, 1/4096 folded
__device__ float2 g_tw512[512];      // W4096^j
__device__ float2 g_t8[64];          // W4096^(8j)  = W512^j
__device__ float2 g_t64[8];          // W4096^(64j) = W64^j

struct __align__(16) Smem {
    float2 buf0[TLEN];     // Y1 path -> modes01 (natural, PH layout)
    float2 buf1[TLEN];     // spectrum park, then Y2 path -> mode2 in .x
    float2 tw512[512];
    float2 t8[64];
    float2 t64[8];
    int    hist[8][36];
    float  red[16][20];
    float  totals[20];
    int    cnt[36];
    float  xnyq;
};

__device__ __forceinline__ float2 cadd(float2 a, float2 b){ return make_float2(a.x+b.x, a.y+b.y); }
__device__ __forceinline__ float2 csub(float2 a, float2 b){ return make_float2(a.x-b.x, a.y-b.y); }
__device__ __forceinline__ float2 cmul(float2 a, float2 b){
    return make_float2(fmaf(a.x,b.x,-a.y*b.y), fmaf(a.x,b.y, a.y*b.x));
}
__device__ __forceinline__ float2 conj2(float2 a){ return make_float2(a.x, -a.y); }

__global__ void init_tables()
{
    int j = blockIdx.x * blockDim.x + threadIdx.x;   // 0..4095
    float sv, cv;
    if (j < 512) {
        sincospif(-(float)j * (1.0f/2048.0f), &sv, &cv);  // -2pi j/4096
        g_tw512[j] = make_float2(cv, sv);
    }
    if (j < 64) {
        sincospif(-(float)j * (1.0f/256.0f), &sv, &cv);   // -2pi 8j/4096
        g_t8[j] = make_float2(cv, sv);
    }
    if (j < 8) {
        sincospif(-(float)j * (1.0f/32.0f), &sv, &cv);    // -2pi 64j/4096
        g_t64[j] = make_float2(cv, sv);
    }
    // frequency bin at digit-reversed position j (4 base-8 digits)
    int K = ((j&7)<<9) | (((j>>3)&7)<<6) | (((j>>6)&7)<<3) | ((j>>9)&7);
    float f = (float)((K < 2048) ? K : (K - 4096)) * (1.0f/4096.0f);
    const float h = 0.5f * (1.0f/4096.0f);
    float u;
    u = f + 0.5f; float a0 = expf(-12.5f*u*u);
    u = f - 0.5f; float a1 = expf(-12.5f*u*u);
    u = f - 0.3f; float b0 = expf(-12.5f*u*u);
    u = f + 0.3f; float b1 = expf(-12.5f*u*u);
    u = f - 0.1f; float c0 = expf(-12.5f*u*u);
    u = f + 0.1f; float c1 = expf(-12.5f*u*u);
    g_masks_br[j] = make_float4(h*(a0+a1), h*(b0+b1), h*(c0+c1), 0.f);
}

// In-place DFT-8: x[r] <- sum_n x[n] * W8^(+-rn)
template<bool INV>
__device__ __forceinline__ void dft8(float2 x[8])
{
    float2 t0=cadd(x[0],x[4]), t1=cadd(x[1],x[5]), t2=cadd(x[2],x[6]), t3=cadd(x[3],x[7]);
    float2 u0=csub(x[0],x[4]), u1=csub(x[1],x[5]), u2=csub(x[2],x[6]), u3=csub(x[3],x[7]);
    const float C8 = 0.70710678118654752f;
    const float2 om  = INV ? make_float2( C8,  C8) : make_float2( C8, -C8);
    const float2 om3 = INV ? make_float2(-C8,  C8) : make_float2(-C8, -C8);
    float2 v1 = cmul(u1, om);
    float2 v2 = INV ? make_float2(-u2.y, u2.x) : make_float2(u2.y, -u2.x);
    float2 v3 = cmul(u3, om3);
    float2 s02=cadd(t0,t2), d02=csub(t0,t2), s13=cadd(t1,t3), d13=csub(t1,t3);
    float2 jd = make_float2(-d13.y, d13.x);
    x[0] = cadd(s02, s13);
    x[4] = csub(s02, s13);
    x[2] = INV ? cadd(d02, jd) : csub(d02, jd);
    x[6] = INV ? csub(d02, jd) : cadd(d02, jd);
    float2 so=cadd(u0,v2), doo=csub(u0,v2), s13o=cadd(v1,v3), d13o=csub(v1,v3);
    float2 jdo = make_float2(-d13o.y, d13o.x);
    x[1] = cadd(so, s13o);
    x[5] = csub(so, s13o);
    x[3] = INV ? cadd(doo, jdo) : csub(doo, jdo);
    x[7] = INV ? csub(doo, jdo) : cadd(doo, jdo);
}

// In-place forward DIF stage, M = 2^MB; wb = W_L^j (L = 8M), twiddle AFTER dft.
template<int MB>
__device__ __forceinline__ void stage_fwd(float2* __restrict__ buf, int tid, float2 wb)
{
    const int M = 1 << MB;
    const int j = tid & (M-1);
    const int base = ((tid >> MB) << (MB+3)) | j;
    float2 x[8];
    #pragma unroll
    for (int k = 0; k < 8; ++k) x[k] = buf[PH(base + (k<<MB))];
    dft8<false>(x);
    float2 w = wb;
    #pragma unroll
    for (int r = 1; r < 8; ++r) { x[r] = cmul(x[r], w); if (r < 7) w = cmul(w, wb); }
    #pragma unroll
    for (int k = 0; k < 8; ++k) buf[PH(base + (k<<MB))] = x[k];
}

// In-place single-buffer inverse DIT stage, twiddle BEFORE dft. wb pre-conjugated.
template<int MB>
__device__ __forceinline__ void stage_inv(float2* __restrict__ buf, int tid, float2 wb)
{
    const int M = 1 << MB;
    const int j = tid & (M-1);
    const int base = ((tid >> MB) << (MB+3)) | j;
    float2 x[8];
    #pragma unroll
    for (int k = 0; k < 8; ++k) x[k] = buf[PH(base + (k<<MB))];
    float2 w = wb;
    #pragma unroll
    for (int r = 1; r < 8; ++r) { x[r] = cmul(x[r], w); if (r < 7) w = cmul(w, wb); }
    dft8<true>(x);
    #pragma unroll
    for (int k = 0; k < 8; ++k) buf[PH(base + (k<<MB))] = x[k];
}

// Lehmer code of stable argsort of (a,b,c), matching reference id formula.
__device__ __forceinline__ int permid(float a, float b, float c)
{
    int i0 = (a <= b) ? 1 : 0;
    int i1 = (a <= c) ? 1 : 0;
    int i2 = (b <= c) ? 1 : 0;
    int idx = (i0 << 2) | (i1 << 1) | i2;
    const unsigned LUT = (5u<<0)|(3u<<4)|(0u<<8)|(2u<<12)|(4u<<16)|(0u<<20)|(1u<<24)|(0u<<28);
    return (int)((LUT >> (idx*4)) & 0xFu);
}

__device__ __forceinline__ constexpr int qidx(int k, int l) { return k*(9-k)/2 + l; }

__global__ __launch_bounds__(NTHREADS, 3)
void tfmptf_kernel(const float* __restrict__ in, float* __restrict__ out)
{
    extern __shared__ char smraw[];
    Smem& sm = *reinterpret_cast<Smem*>(smraw);
    const int tid = threadIdx.x;
    const int bid = blockIdx.x;          // bid = b*64 + d
    const int d = bid & 63;
    const int b = bid >> 6;
    const int warp = tid >> 5;
    const int lane = tid & 31;

    // --- tables + hist zero (no barrier needed before stage 0: own-index use) ---
    float2 myw = __ldg(&g_tw512[tid]);
    sm.tw512[tid] = myw;
    if (tid < 64) sm.t8[tid]  = __ldg(&g_t8[tid]);
    if (tid < 8)  sm.t64[tid] = __ldg(&g_t64[tid]);
    for (int i = tid; i < 8*36; i += NTHREADS) ((int*)sm.hist)[i] = 0;

    // --- forward stage 0 (M=512): gmem -> butterfly -> buf0 ---
    const float* xin = in + ((long)b * TLEN) * 64 + d;
    {
        float2 x[8];
        #pragma unroll
        for (int k = 0; k < 8; ++k)
            x[k] = make_float2(__ldg(&xin[(long)(tid + (k<<9)) * 64]), 0.0f);
        dft8<false>(x);
        float2 w = myw;
        #pragma unroll
        for (int r = 1; r < 8; ++r) { x[r] = cmul(x[r], w); if (r < 7) w = cmul(w, myw); }
        #pragma unroll
        for (int k = 0; k < 8; ++k) sm.buf0[PH(tid + (k<<9))] = x[k];
    }
    __syncthreads();

    // --- forward stages 1 (M=64), 2 (M=8) ---
    stage_fwd<6>(sm.buf0, tid, sm.t8[tid & 63]);
    __syncthreads();
    stage_fwd<3>(sm.buf0, tid, sm.t64[tid & 7]);
    __syncthreads();

    // --- fused: fwd stage 3 (trivial tw) + masks + inv stage 0, one 8-array live ---
    {
        const int base = tid << 3;
        float2 y[8];
        #pragma unroll
        for (int k = 0; k < 8; ++k) y[k] = sm.buf0[PH(base + k)];
        dft8<false>(y);
        if (tid == 0) sm.xnyq = y[4].x;          // pos 4 = rev(2048)
        #pragma unroll
        for (int k = 0; k < 8; ++k) sm.buf1[PH(base + k)] = y[k];  // park spectrum
        // Y1 path
        #pragma unroll
        for (int k = 0; k < 8; ++k) {
            float4 S = __ldg(&g_masks_br[base + k]);
            float2 Y = y[k];
            y[k] = make_float2(Y.x*S.x - Y.y*S.y, Y.x*S.y + Y.y*S.x);
        }
        dft8<true>(y);
        #pragma unroll
        for (int k = 0; k < 8; ++k) sm.buf0[PH(base + k)] = y[k];
        // Y2 path (reload parked spectrum; own slots, no barrier)
        #pragma unroll
        for (int k = 0; k < 8; ++k) {
            float2 Y = sm.buf1[PH(base + k)];
            float sz = __ldg(&g_masks_br[base + k]).z;
            y[k] = make_float2(Y.x*sz, Y.y*sz);
        }
        dft8<true>(y);
        #pragma unroll
        for (int k = 0; k < 8; ++k) sm.buf1[PH(base + k)] = y[k];
    }
    __syncthreads();

    // --- inverse stages: L=64 (M=8), L=512 (M=64); single-buffer calls ---
    stage_inv<3>(sm.buf0, tid, conj2(sm.t64[tid & 7]));
    stage_inv<3>(sm.buf1, tid, conj2(sm.t64[tid & 7]));
    __syncthreads();
    stage_inv<6>(sm.buf0, tid, conj2(sm.t8[tid & 63]));
    stage_inv<6>(sm.buf1, tid, conj2(sm.t8[tid & 63]));
    __syncthreads();

    // --- final inverse stage (L=4096, M=512); one buffer at a time ---
    {
        float2 wb = conj2(myw);
        float2 x[8];
        #pragma unroll
        for (int k = 0; k < 8; ++k) x[k] = sm.buf0[PH(tid + (k<<9))];
        float2 w = wb;
        #pragma unroll
        for (int r = 1; r < 8; ++r) { x[r] = cmul(x[r], w); if (r < 7) w = cmul(w, wb); }
        dft8<true>(x);
        #pragma unroll
        for (int k = 0; k < 8; ++k) sm.buf0[PH(tid + (k<<9))] = x[k];
        #pragma unroll
        for (int k = 0; k < 8; ++k) x[k] = sm.buf1[PH(tid + (k<<9))];
        w = wb;
        #pragma unroll
        for (int r = 1; r < 8; ++r) { x[r] = cmul(x[r], w); if (r < 7) w = cmul(w, wb); }
        dft8<true>(x);
        #pragma unroll
        for (int k = 0; k < 8; ++k) sm.buf1[PH(tid + (k<<9))] = x[k];
    }

    // --- Nyquist rank-1 corrections ---
    const float xn = sm.xnyq * (1.0f/4096.0f);
    const float eg[3] = {
        0.49999813667341397f * xn,
        0.30309759854236545f * xn,
        0.06211314334918520f * xn
    };

    // --- correlation moments (own slots, no barrier; e[] squared immediately) ---
    float S[5]; float Q[15];
    #pragma unroll
    for (int i = 0; i < 5; ++i) S[i] = 0.f;
    #pragma unroll
    for (int i = 0; i < 15; ++i) Q[i] = 0.f;
    const float pe = (tid & 1) ? -1.f : 1.f;
    #pragma unroll
    for (int k = 0; k < 8; ++k) {
        int a = PH(tid + (k<<9));
        float2 z = sm.buf0[a];
        float m2 = sm.buf1[a].x;
        float e[5];
        float t;
        t = z.x + pe*eg[0]; e[0] = t*t;
        t = z.y + pe*eg[1]; e[1] = t*t;
        t = m2  + pe*eg[2]; e[2] = t*t;
        t = m2  - pe*eg[2]; e[3] = t*t;
        t = z.y - pe*eg[1]; e[4] = t*t;
        #pragma unroll
        for (int kk = 0; kk < 5; ++kk) {
            S[kk] += e[kk];
            #pragma unroll
            for (int l = kk; l < 5; ++l)
                Q[qidx(kk,l)] = fmaf(e[kk], e[l], Q[qidx(kk,l)]);
        }
    }
    {
        float vvv[20];
        #pragma unroll
        for (int j = 0; j < 5; ++j)  vvv[j]   = S[j];
        #pragma unroll
        for (int j = 0; j < 15; ++j) vvv[5+j] = Q[j];
        #pragma unroll
        for (int j = 0; j < 20; ++j)
            #pragma unroll
            for (int off = 16; off; off >>= 1)
                vvv[j] += __shfl_down_sync(0xffffffffu, vvv[j], off);
        if (lane == 0)
            #pragma unroll
            for (int j = 0; j < 20; ++j) sm.red[warp][j] = vvv[j];
    }
    __syncthreads();   // modes stores + red visible

    // --- sliding-window permutation transitions: 5 (mode,sign) passes ---
    {
        const int w0 = tid * 8;
        #pragma unroll
        for (int gg = 0; gg < 3; ++gg) {
            const int nsign = (gg == 0) ? 1 : 2;
            #pragma unroll
            for (int sv = 0; sv < 2; ++sv) {
                if (sv >= nsign) break;
                const float eps = (sv == 0) ? eg[gg] : -eg[gg];
                float vv[11];
                #pragma unroll
                for (int i = 0; i < 11; ++i) {
                    int e = w0 + i; e = (e < TLEN) ? e : (TLEN - 1);
                    int a = PH(e);
                    float m = (gg == 0) ? sm.buf0[a].x
                            : ((gg == 1) ? sm.buf0[a].y : sm.buf1[a].x);
                    vv[i] = m + (((w0 + i) & 1) ? -eps : eps);
                }
                int id[9];
                #pragma unroll
                for (int i = 0; i < 9; ++i)
                    id[i] = permid(vv[i], vv[i+1], vv[i+2]);
                #pragma unroll
                for (int i = 0; i < 8; ++i) {
                    bool valid = (w0 + i) < 4093;
                    int code = valid ? (id[i]*6 + id[i+1]) : 36;
                    unsigned grp = __match_any_sync(0xffffffffu, code);
                    if (valid && (int)(__ffs(grp) - 1) == lane)
                        atomicAdd(&sm.hist[warp >> 1][code], __popc(grp));
                }
            }
        }
    }
    __syncthreads();

    if (tid < 36) {
        int ctot = 0;
        #pragma unroll
        for (int w = 0; w < 8; ++w) ctot += sm.hist[w][tid];
        sm.cnt[tid] = ctot;
    }
    if (tid < 20) {
        float tot = 0.f;
        #pragma unroll
        for (int w = 0; w < 16; ++w) tot += sm.red[w][tid];
        sm.totals[tid] = tot;
    }
    __syncthreads();

    float* outbd = out + (long)bid * 46;
    if (tid < 36) {
        int pp = tid / 6;
        int rs = 0;
        #pragma unroll
        for (int qq = 0; qq < 6; ++qq) rs += sm.cnt[pp*6 + qq];
        float denom = rs ? (float)rs : 1.0f;
        outbd[tid] = (float)sm.cnt[tid] / denom;
    }
    if (tid == 0) {
        const float invT = 1.0f / 4096.0f;
        float cov[15];
        #pragma unroll
        for (int k = 0; k < 5; ++k)
            #pragma unroll
            for (int l = k; l < 5; ++l)
                cov[qidx(k,l)] = sm.totals[5 + qidx(k,l)]
                               - sm.totals[k]*sm.totals[l]*invT;
        float dstd[5];
        #pragma unroll
        for (int k = 0; k < 5; ++k) dstd[k] = sqrtf(fmaxf(cov[qidx(k,k)], 0.f));
        int oi = 36;
        #pragma unroll
        for (int k = 0; k < 5; ++k) {
            #pragma unroll
            for (int l = k+1; l < 5; ++l) {
                float den = dstd[k] * dstd[l];
                float r = (den > 0.f) ? cov[qidx(k,l)] / den : 0.f;
                r = fminf(1.f, fmaxf(-1.f, r));
                outbd[oi++] = r;
            }
        }
    }
}

extern "C" void kernel_launch(void* const* d_in, const int* in_sizes, int n_in,
                              void* d_out, int out_size)
{
    (void)in_sizes; (void)n_in; (void)out_size;
    const float* in = (const float*)d_in[0];
    float* out = (float*)d_out;
    init_tables<<<8, 512>>>();
    cudaFuncSetAttribute(tfmptf_kernel, cudaFuncAttributeMaxDynamicSharedMemorySize,
                         (int)sizeof(Smem));
    tfmptf_kernel<<<1024, NTHREADS, sizeof(Smem)>>>(in, out);
}